// round 15
// baseline (speedup 1.0000x reference)
#include <cuda_runtime.h>

#define Bn 64
#define Nn 4096
#define Kk 11
#define KP 12
#define Dd 192
#define HIDn 128
#define Tt 128
#define XST 196
#define EPSF 1e-8f
#define LN_EPSF 1e-5f
#define SCALEF 0.07216878364870323f

typedef unsigned long long ull;

__device__ __forceinline__ ull pk2(float x) {
    ull r; asm("mov.b64 %0, {%1, %1};" : "=l"(r) : "f"(x)); return r;
}
__device__ __forceinline__ ull f2fma(ull a, ull b, ull c) {
    ull d; asm("fma.rn.f32x2 %0, %1, %2, %3;" : "=l"(d) : "l"(a), "l"(b), "l"(c)); return d;
}
__device__ __forceinline__ ull f2add(ull a, ull b) {
    ull d; asm("add.rn.f32x2 %0, %1, %2;" : "=l"(d) : "l"(a), "l"(b)); return d;
}
__device__ __forceinline__ float2 up2(ull v) {
    float lo, hi; asm("mov.b64 {%0, %1}, %2;" : "=f"(lo), "=f"(hi) : "l"(v));
    return make_float2(lo, hi);
}
__device__ __forceinline__ void fma12(ull acc[6], const float* p, ull xx) {
    ulonglong2 q0 = *(const ulonglong2*)p;
    ulonglong2 q1 = *(const ulonglong2*)(p + 4);
    ulonglong2 q2 = *(const ulonglong2*)(p + 8);
    acc[0] = f2fma(q0.x, xx, acc[0]); acc[1] = f2fma(q0.y, xx, acc[1]);
    acc[2] = f2fma(q1.x, xx, acc[2]); acc[3] = f2fma(q1.y, xx, acc[3]);
    acc[4] = f2fma(q2.x, xx, acc[4]); acc[5] = f2fma(q2.y, xx, acc[5]);
}
__device__ __forceinline__ void unpk11(const ull a6[6], float* o) {
#pragma unroll
    for (int j = 0; j < 6; j++) {
        float2 f = up2(a6[j]);
        o[2 * j] = f.x;
        if (2 * j + 1 < Kk) o[2 * j + 1] = f.y;
    }
}

__device__ float g_slots[Bn * Kk * Dd];
__device__ float g_h[Bn * Kk * Dd];
__device__ float g_w2k[Bn * Kk * Dd];
__device__ float g_w2sum[Bn * Kk];
__device__ float g_cc[Bn * Kk];
__device__ float g_R[Bn * Kk * Dd];
__device__ float g_s1[Bn * Kk];
__device__ float g_s2[Bn * Kk];
__device__ float g_WqT[Dd * Dd];
__device__ float g_WvT[Dd * Dd];
__device__ float g_W1T[HIDn * Dd];
__device__ float g_W2T[Dd * HIDn];

// ---------------- init ----------------
__global__ void k_init(const float* __restrict__ noise, const float* __restrict__ smu,
                       const float* __restrict__ ssig, const float* __restrict__ Wq,
                       const float* __restrict__ Wv, const float* __restrict__ W1,
                       const float* __restrict__ W2) {
    const int T0 = Bn * Kk * Dd;
    const int T1 = T0 + Dd * Dd;
    const int T2 = T1 + Dd * Dd;
    const int T3 = T2 + Dd * HIDn;
    const int T4 = T3 + HIDn * Dd;
    for (int i = blockIdx.x * blockDim.x + threadIdx.x; i < T4; i += gridDim.x * blockDim.x) {
        if (i < T0) { int d = i % Dd; g_slots[i] = smu[d] + ssig[d] * noise[i]; }
        else if (i < T1) { int i2 = i - T0; g_WqT[(i2 % Dd) * Dd + i2 / Dd] = Wq[i2]; }
        else if (i < T2) { int i2 = i - T1; g_WvT[(i2 % Dd) * Dd + i2 / Dd] = Wv[i2]; }
        else if (i < T3) { int i2 = i - T2; g_W1T[(i2 % HIDn) * Dd + i2 / HIDn] = W1[i2]; }
        else { int i2 = i - T3; g_W2T[(i2 % Dd) * HIDn + i2 / Dd] = W2[i2]; }
    }
}

// ---------------- iter-0 slot preprocessing (unchanged) ----------------
__global__ __launch_bounds__(192) void k_pre(const float* __restrict__ lnw_s,
                                             const float* __restrict__ lnb_s,
                                             const float* __restrict__ bq,
                                             const float* __restrict__ Wk,
                                             const float* __restrict__ bk,
                                             const float* __restrict__ lnw_in,
                                             const float* __restrict__ lnb_in) {
    __shared__ float snt[Dd * KP];
    __shared__ float qT[Dd * KP];
    __shared__ float red[24];
    int b = blockIdx.x, t = threadIdx.x, wid = t >> 5, lane = t & 31;
    if (t < 24) red[t] = 0.f;
    snt[t * KP + 11] = 0.f;

    for (int r = wid; r < Kk; r += 6) {
        float v[6], s = 0.f;
#pragma unroll
        for (int i = 0; i < 6; i++) { v[i] = g_slots[(b * Kk + r) * Dd + lane + 32 * i]; s += v[i]; }
#pragma unroll
        for (int o = 16; o; o >>= 1) s += __shfl_xor_sync(~0u, s, o);
        float mu = s * (1.0f / Dd), q = 0.f;
#pragma unroll
        for (int i = 0; i < 6; i++) { float d = v[i] - mu; q += d * d; }
#pragma unroll
        for (int o = 16; o; o >>= 1) q += __shfl_xor_sync(~0u, q, o);
        float rstd = rsqrtf(q * (1.0f / Dd) + LN_EPSF);
#pragma unroll
        for (int i = 0; i < 6; i++) {
            int d = lane + 32 * i;
            snt[d * KP + r] = (v[i] - mu) * rstd * lnw_s[d] + lnb_s[d];
        }
    }
    __syncthreads();

    ull a6[6];
#pragma unroll
    for (int j = 0; j < 6; j++) a6[j] = 0ull;
    {
        const float4* w4 = (const float4*)(g_WqT + t * Dd);
#pragma unroll 4
        for (int c = 0; c < 48; c++) {
            float4 w = __ldg(&w4[c]);
            fma12(a6, &snt[(4 * c + 0) * KP], pk2(w.x));
            fma12(a6, &snt[(4 * c + 1) * KP], pk2(w.y));
            fma12(a6, &snt[(4 * c + 2) * KP], pk2(w.z));
            fma12(a6, &snt[(4 * c + 3) * KP], pk2(w.w));
        }
    }
    float qa[Kk];
    unpk11(a6, qa);
    float bqv = bq[t];
#pragma unroll
    for (int r = 0; r < Kk; r++) { qa[r] += bqv; qT[t * KP + r] = qa[r]; }
    qT[t * KP + 11] = 0.f;
    __syncthreads();

#pragma unroll
    for (int j = 0; j < 6; j++) a6[j] = 0ull;
    {
        const float4* w4 = (const float4*)(Wk + t * Dd);
#pragma unroll 4
        for (int c = 0; c < 48; c++) {
            float4 w = __ldg(&w4[c]);
            fma12(a6, &qT[(4 * c + 0) * KP], pk2(w.x));
            fma12(a6, &qT[(4 * c + 1) * KP], pk2(w.y));
            fma12(a6, &qT[(4 * c + 2) * KP], pk2(w.z));
            fma12(a6, &qT[(4 * c + 3) * KP], pk2(w.w));
        }
    }
    float qt[Kk];
    unpk11(a6, qt);
    float lwv = lnw_in[t], lbv = lnb_in[t], bkv = bk[t];
    float ws[Kk], cp[Kk];
#pragma unroll
    for (int r = 0; r < Kk; r++) {
        float w2 = qt[r] * SCALEF * lwv;
        g_w2k[(b * Kk + r) * Dd + t] = w2;
        ws[r] = w2;
        cp[r] = (lbv * qt[r] + qa[r] * bkv) * SCALEF;
    }
#pragma unroll
    for (int r = 0; r < Kk; r++) {
        float a = ws[r], c = cp[r];
#pragma unroll
        for (int o = 16; o; o >>= 1) {
            a += __shfl_xor_sync(~0u, a, o);
            c += __shfl_xor_sync(~0u, c, o);
        }
        if (lane == 0) { atomicAdd(&red[r], a); atomicAdd(&red[12 + r], c); }
    }
    __syncthreads();
    if (t < Kk) {
        g_w2sum[b * Kk + t] = red[t];
        g_cc[b * Kk + t] = red[12 + t];
        g_s1[b * Kk + t] = 0.f;
        g_s2[b * Kk + t] = 0.f;
    }
    for (int i = t; i < Kk * Dd; i += 192) g_R[b * Kk * Dd + i] = 0.f;
}

// ---------------- attention pass: R9-exact (256 threads, 2 threads/token) --------
__global__ __launch_bounds__(256, 2) void k_attn(const float* __restrict__ x,
                                                 float* __restrict__ attn_out, int wr) {
    extern __shared__ float sm[];
    float* Xs = sm;
    float* Ws = sm + Tt * XST;
    float* A1 = Ws;
    int b = blockIdx.y, tid = threadIdx.x;
    int lane = tid & 31, warp = tid >> 5;
    int half = lane >> 4;
    int t = warp * 16 + (lane & 15);
    int n0 = blockIdx.x * Tt;

    const float* xb = x + ((size_t)(b * Nn + n0)) * Dd;
    for (int i = tid * 4; i < Tt * Dd; i += 256 * 4) {
        float4 v = __ldcs((const float4*)(xb + i));
        int tt = i / Dd, d = i - tt * Dd;
        *(float4*)&Xs[tt * XST + d] = v;
    }
    const float* wsrc = g_w2k + b * Kk * Dd;
    for (int i = tid; i < Kk * Dd; i += 256) Ws[i] = wsrc[i];
    __syncthreads();

    ull aA[Kk], aB[Kk];
#pragma unroll
    for (int k = 0; k < Kk; k++) { aA[k] = 0ull; aB[k] = 0ull; }
    ull sS = 0ull, sQ = 0ull;
    const int cbase = half * 96;
    const ulonglong2* xr2 = (const ulonglong2*)(Xs + t * XST + cbase);
#pragma unroll 2
    for (int c = 0; c < 24; c++) {
        ulonglong2 xv = xr2[c];
        sS = f2add(sS, f2add(xv.x, xv.y));
        sQ = f2fma(xv.x, xv.x, sQ); sQ = f2fma(xv.y, xv.y, sQ);
        const float* wrow = &Ws[cbase + c * 4];
#pragma unroll
        for (int k = 0; k < Kk; k++) {
            ulonglong2 wv = *(const ulonglong2*)&wrow[k * Dd];
            aA[k] = f2fma(xv.x, wv.x, aA[k]);
            aB[k] = f2fma(xv.y, wv.y, aB[k]);
        }
    }
    float dots[Kk];
#pragma unroll
    for (int k = 0; k < Kk; k++) {
        float2 fa = up2(aA[k]), fb = up2(aB[k]);
        dots[k] = (fa.x + fa.y) + (fb.x + fb.y);
    }
    float2 sf = up2(sS), qf = up2(sQ);
    float sSf = sf.x + sf.y, sQf = qf.x + qf.y;
    sSf += __shfl_xor_sync(~0u, sSf, 16);
    sQf += __shfl_xor_sync(~0u, sQf, 16);
#pragma unroll
    for (int k = 0; k < Kk; k++) dots[k] += __shfl_xor_sync(~0u, dots[k], 16);

    float mu = sSf * (1.0f / Dd);
    float rs = rsqrtf(sQf * (1.0f / Dd) - mu * mu + LN_EPSF);
    float rm = rs * mu;
    float dk[Kk];
#pragma unroll
    for (int k = 0; k < Kk; k++)
        dk[k] = rs * dots[k] - rm * __ldg(&g_w2sum[b * Kk + k]) + __ldg(&g_cc[b * Kk + k]);
    float mx = dk[0];
#pragma unroll
    for (int k = 1; k < Kk; k++) mx = fmaxf(mx, dk[k]);
    float sum = 0.f;
#pragma unroll
    for (int k = 0; k < Kk; k++) { dk[k] = __expf(dk[k] - mx); sum += dk[k]; }
    float inv = __fdividef(1.0f, sum);
#pragma unroll
    for (int k = 0; k < Kk; k++) dk[k] = fmaf(dk[k], inv, EPSF);

    if (wr && half == 0) {
        int n = n0 + t;
#pragma unroll
        for (int k = 0; k < Kk; k++)
            attn_out[((size_t)(b * Kk + k)) * Nn + n] = dk[k];
    }
#pragma unroll
    for (int k = 0; k < Kk; k++) {
        float s1v = half ? 0.f : dk[k];
        float s2v = half ? 0.f : dk[k] * rm;
#pragma unroll
        for (int o = 16; o; o >>= 1) {
            s1v += __shfl_xor_sync(~0u, s1v, o);
            s2v += __shfl_xor_sync(~0u, s2v, o);
        }
        if (lane == 0) {
            atomicAdd(&g_s1[b * Kk + k], s1v);
            atomicAdd(&g_s2[b * Kk + k], s2v);
        }
    }
    __syncthreads();
    if (half == 0) {
#pragma unroll
        for (int k = 0; k < Kk; k++) A1[t * KP + k] = dk[k] * rs;
        A1[t * KP + 11] = 0.f;
    }
    __syncthreads();

    float* Rb = g_R + b * Kk * Dd;
    for (int w = tid; w < 384; w += 256) {
        int h = (w >= 192) ? 1 : 0;
        int d = w - h * 192;
        ull c6[6];
#pragma unroll
        for (int j = 0; j < 6; j++) c6[j] = 0ull;
        int t0 = h * 64;
#pragma unroll 2
        for (int tt = t0; tt < t0 + 64; tt++) {
            fma12(c6, &A1[tt * KP], pk2(Xs[tt * XST + d]));
        }
#pragma unroll
        for (int j = 0; j < 6; j++) {
            float2 f = up2(c6[j]);
            atomicAdd(&Rb[(2 * j) * Dd + d], f.x);
            if (2 * j + 1 < Kk) atomicAdd(&Rb[(2 * j + 1) * Dd + d], f.y);
        }
    }
}

// ---------------- GRU: R13-exact (576 threads, lane-pair e-split) ----------------
__global__ __launch_bounds__(576) void k_gru(const float* __restrict__ bv,
                                             const float* __restrict__ Wih,
                                             const float* __restrict__ Whh,
                                             const float* __restrict__ bih,
                                             const float* __restrict__ bhh,
                                             const float* __restrict__ lnw_in,
                                             const float* __restrict__ lnb_in) {
    __shared__ float uT[Dd * KP], spT[Dd * KP], vT[Dd * KP];
    __shared__ float P0[96 * KP], P1[96 * KP], PXn[96 * KP], PHn[96 * KP];
    __shared__ float sinv[Kk], s2s[Kk];
    int hh = blockIdx.x, b = blockIdx.y, tid = threadIdx.x;
    int lane = tid & 31, warp = tid >> 5;
    int half = lane >> 4;
    int col = warp * 16 + (lane & 15);

    if (tid < Kk) {
        sinv[tid] = __fdividef(1.0f, g_s1[b * Kk + tid]);
        s2s[tid] = g_s2[b * Kk + tid];
    }
    __syncthreads();
    for (int i = tid; i < Dd; i += 576) { uT[i * KP + 11] = 0.f; spT[i * KP + 11] = 0.f; }
    for (int i = tid; i < Kk * Dd; i += 576) {
        int r = i / Dd, d = i - r * Dd;
        float R = g_R[b * Kk * Dd + i];
        uT[d * KP + r] = lnw_in[d] * (R - s2s[r]) * sinv[r] + lnb_in[d];
        spT[d * KP + r] = g_slots[b * Kk * Dd + i];
    }
    __syncthreads();

    if (col < Dd) {
        ull a6[6];
#pragma unroll
        for (int j = 0; j < 6; j++) a6[j] = 0ull;
        const float4* w4 = (const float4*)(g_WvT + col * Dd + half * 96);
        const float* uu = uT + half * 96 * KP;
#pragma unroll 4
        for (int c = 0; c < 24; c++) {
            float4 w = __ldg(&w4[c]);
            fma12(a6, &uu[(4 * c + 0) * KP], pk2(w.x));
            fma12(a6, &uu[(4 * c + 1) * KP], pk2(w.y));
            fma12(a6, &uu[(4 * c + 2) * KP], pk2(w.z));
            fma12(a6, &uu[(4 * c + 3) * KP], pk2(w.w));
        }
        float vv[Kk];
        unpk11(a6, vv);
#pragma unroll
        for (int r = 0; r < Kk; r++) vv[r] += __shfl_xor_sync(~0u, vv[r], 16);
        if (half == 0) {
            float bvv = bv[col];
#pragma unroll
            for (int r = 0; r < Kk; r++) vT[col * KP + r] = vv[r] + bvv;
            vT[col * KP + 11] = 0.f;
        }
    }
    __syncthreads();

    {
        int g = col / 96, tl = col - g * 96;
        int j = g * Dd + hh * 96 + tl;
        ull ax6[6], ah6[6];
#pragma unroll
        for (int jj = 0; jj < 6; jj++) { ax6[jj] = 0ull; ah6[jj] = 0ull; }
        const float4* wi4 = (const float4*)(Wih + j * Dd + half * 96);
        const float4* wh4 = (const float4*)(Whh + j * Dd + half * 96);
        const float* vv_ = vT + half * 96 * KP;
        const float* ss_ = spT + half * 96 * KP;
#pragma unroll 4
        for (int c = 0; c < 24; c++) {
            float4 wi = __ldg(&wi4[c]);
            float4 wh = __ldg(&wh4[c]);
            fma12(ax6, &vv_[(4 * c + 0) * KP], pk2(wi.x));
            fma12(ax6, &vv_[(4 * c + 1) * KP], pk2(wi.y));
            fma12(ax6, &vv_[(4 * c + 2) * KP], pk2(wi.z));
            fma12(ax6, &vv_[(4 * c + 3) * KP], pk2(wi.w));
            fma12(ah6, &ss_[(4 * c + 0) * KP], pk2(wh.x));
            fma12(ah6, &ss_[(4 * c + 1) * KP], pk2(wh.y));
            fma12(ah6, &ss_[(4 * c + 2) * KP], pk2(wh.z));
            fma12(ah6, &ss_[(4 * c + 3) * KP], pk2(wh.w));
        }
        float axf[Kk], ahf[Kk];
        unpk11(ax6, axf); unpk11(ah6, ahf);
#pragma unroll
        for (int r = 0; r < Kk; r++) {
            axf[r] += __shfl_xor_sync(~0u, axf[r], 16);
            ahf[r] += __shfl_xor_sync(~0u, ahf[r], 16);
        }
        if (half == 0) {
            float bi = bih[j], bh = bhh[j];
            if (g == 0) {
#pragma unroll
                for (int r = 0; r < Kk; r++) P0[tl * KP + r] = axf[r] + ahf[r] + bi + bh;
            } else if (g == 1) {
#pragma unroll
                for (int r = 0; r < Kk; r++) P1[tl * KP + r] = axf[r] + ahf[r] + bi + bh;
            } else {
#pragma unroll
                for (int r = 0; r < Kk; r++) { PXn[tl * KP + r] = axf[r] + bi; PHn[tl * KP + r] = ahf[r] + bh; }
            }
        }
    }
    __syncthreads();
    for (int i = tid; i < Kk * 96; i += 576) {
        int r = i / 96, tl2 = i - r * 96, tg = hh * 96 + tl2;
        float rg = 1.0f / (1.0f + __expf(-P0[tl2 * KP + r]));
        float zg = 1.0f / (1.0f + __expf(-P1[tl2 * KP + r]));
        float ng = tanhf(fmaf(rg, PHn[tl2 * KP + r], PXn[tl2 * KP + r]));
        float hp = spT[tg * KP + r];
        g_h[(b * Kk + r) * Dd + tg] = (1.0f - zg) * ng + zg * hp;
    }
}

// -------- LN + MLP + residual + fused pre: 768 threads, lane-QUAD split --------
__global__ __launch_bounds__(768) void k_mlp(const float* __restrict__ lnw_m,
                                             const float* __restrict__ lnb_m,
                                             const float* __restrict__ b1,
                                             const float* __restrict__ b2,
                                             const float* __restrict__ lnw_s,
                                             const float* __restrict__ lnb_s,
                                             const float* __restrict__ bq,
                                             const float* __restrict__ Wk,
                                             const float* __restrict__ bk,
                                             const float* __restrict__ lnw_in,
                                             const float* __restrict__ lnb_in,
                                             float* __restrict__ slots_out, int last) {
    __shared__ float hT[Dd * KP];    // LN(h); later slots_new
    __shared__ float m1T[HIDn * KP];
    __shared__ float snt[Dd * KP];   // LN(slots_new)
    __shared__ float qT[Dd * KP];
    __shared__ float red[24];
    int b = blockIdx.x, tid = threadIdx.x;
    int lane = tid & 31, warp = tid >> 5;   // warp 0..23
    int quar = lane >> 3;                   // 0..3
    int col = warp * 8 + (lane & 7);        // 0..191
    if (tid < 24) red[tid] = 0.f;
    if (tid < Dd) { hT[tid * KP + 11] = 0.f; snt[tid * KP + 11] = 0.f; }
    if (tid < HIDn) m1T[tid * KP + 11] = 0.f;

    // LN(h) -> hT : warp-per-slot (warps 0..10)
    if (warp < Kk) {
        int r = warp;
        float v[6], s = 0.f;
#pragma unroll
        for (int i = 0; i < 6; i++) { v[i] = g_h[(b * Kk + r) * Dd + lane + 32 * i]; s += v[i]; }
#pragma unroll
        for (int o = 16; o; o >>= 1) s += __shfl_xor_sync(~0u, s, o);
        float mu = s * (1.0f / Dd), q = 0.f;
#pragma unroll
        for (int i = 0; i < 6; i++) { float d = v[i] - mu; q += d * d; }
#pragma unroll
        for (int o = 16; o; o >>= 1) q += __shfl_xor_sync(~0u, q, o);
        float rstd = rsqrtf(q * (1.0f / Dd) + LN_EPSF);
#pragma unroll
        for (int i = 0; i < 6; i++) {
            int d = lane + 32 * i;
            hT[d * KP + r] = (v[i] - mu) * rstd * lnw_m[d] + lnb_m[d];
        }
    }
    __syncthreads();

    // MLP layer 1: 128 cols, quad e-split (48 each)
    if (col < HIDn) {
        ull a6[6];
#pragma unroll
        for (int j = 0; j < 6; j++) a6[j] = 0ull;
        const float4* w4 = (const float4*)(g_W1T + col * Dd + quar * 48);
        const float* hh_ = hT + quar * 48 * KP;
#pragma unroll 4
        for (int c = 0; c < 12; c++) {
            float4 w = __ldg(&w4[c]);
            fma12(a6, &hh_[(4 * c + 0) * KP], pk2(w.x));
            fma12(a6, &hh_[(4 * c + 1) * KP], pk2(w.y));
            fma12(a6, &hh_[(4 * c + 2) * KP], pk2(w.z));
            fma12(a6, &hh_[(4 * c + 3) * KP], pk2(w.w));
        }
        float vv[Kk];
        unpk11(a6, vv);
#pragma unroll
        for (int r = 0; r < Kk; r++) {
            vv[r] += __shfl_xor_sync(~0u, vv[r], 8);
            vv[r] += __shfl_xor_sync(~0u, vv[r], 16);
        }
        if (quar == 0) {
            float b1v = b1[col];
#pragma unroll
            for (int r = 0; r < Kk; r++) m1T[col * KP + r] = fmaxf(vv[r] + b1v, 0.0f);
        }
    }
    __syncthreads();

    // MLP layer 2 + residual: 192 cols, quad h-split (32 each)
    {
        ull a6[6];
#pragma unroll
        for (int j = 0; j < 6; j++) a6[j] = 0ull;
        const float4* w4 = (const float4*)(g_W2T + col * HIDn + quar * 32);
        const float* mm = m1T + quar * 32 * KP;
#pragma unroll 4
        for (int c = 0; c < 8; c++) {
            float4 w = __ldg(&w4[c]);
            fma12(a6, &mm[(4 * c + 0) * KP], pk2(w.x));
            fma12(a6, &mm[(4 * c + 1) * KP], pk2(w.y));
            fma12(a6, &mm[(4 * c + 2) * KP], pk2(w.z));
            fma12(a6, &mm[(4 * c + 3) * KP], pk2(w.w));
        }
        float acc[Kk];
        unpk11(a6, acc);
#pragma unroll
        for (int r = 0; r < Kk; r++) {
            acc[r] += __shfl_xor_sync(~0u, acc[r], 8);
            acc[r] += __shfl_xor_sync(~0u, acc[r], 16);
        }
        if (quar == 0) {
            float b2v = b2[col];
#pragma unroll
            for (int r = 0; r < Kk; r++) {
                float o = g_h[(b * Kk + r) * Dd + col] + acc[r] + b2v;
                g_slots[(b * Kk + r) * Dd + col] = o;
                if (last) slots_out[(b * Kk + r) * Dd + col] = o;
                hT[col * KP + r] = o;   // slots_new staged for fused pre
            }
        }
    }
    if (last) return;
    __syncthreads();

    // ---- fused pre for next iteration ----
    // LN(slots_new in hT) -> snt
    if (warp < Kk) {
        int r = warp;
        float v[6], s = 0.f;
#pragma unroll
        for (int i = 0; i < 6; i++) { v[i] = hT[(lane + 32 * i) * KP + r]; s += v[i]; }
#pragma unroll
        for (int o = 16; o; o >>= 1) s += __shfl_xor_sync(~0u, s, o);
        float mu = s * (1.0f / Dd), q = 0.f;
#pragma unroll
        for (int i = 0; i < 6; i++) { float d = v[i] - mu; q += d * d; }
#pragma unroll
        for (int o = 16; o; o >>= 1) q += __shfl_xor_sync(~0u, q, o);
        float rstd = rsqrtf(q * (1.0f / Dd) + LN_EPSF);
#pragma unroll
        for (int i = 0; i < 6; i++) {
            int d = lane + 32 * i;
            snt[d * KP + r] = (v[i] - mu) * rstd * lnw_s[d] + lnb_s[d];
        }
    }
    __syncthreads();
    // q = sn @ Wq + bq : quad e-split
    float qa[Kk];
    {
        ull a6[6];
#pragma unroll
        for (int j = 0; j < 6; j++) a6[j] = 0ull;
        const float4* w4 = (const float4*)(g_WqT + col * Dd + quar * 48);
        const float* ss = snt + quar * 48 * KP;
#pragma unroll 4
        for (int c = 0; c < 12; c++) {
            float4 w = __ldg(&w4[c]);
            fma12(a6, &ss[(4 * c + 0) * KP], pk2(w.x));
            fma12(a6, &ss[(4 * c + 1) * KP], pk2(w.y));
            fma12(a6, &ss[(4 * c + 2) * KP], pk2(w.z));
            fma12(a6, &ss[(4 * c + 3) * KP], pk2(w.w));
        }
        unpk11(a6, qa);
        float bqv = bq[col];
#pragma unroll
        for (int r = 0; r < Kk; r++) {
            qa[r] += __shfl_xor_sync(~0u, qa[r], 8);
            qa[r] += __shfl_xor_sync(~0u, qa[r], 16);
            qa[r] += bqv;
        }
        if (quar == 0) {
#pragma unroll
            for (int r = 0; r < Kk; r++) qT[col * KP + r] = qa[r];
            qT[col * KP + 11] = 0.f;
        }
    }
    __syncthreads();
    // qt = Wk @ q : quad d-split
    {
        ull a6[6];
#pragma unroll
        for (int j = 0; j < 6; j++) a6[j] = 0ull;
        const float4* w4 = (const float4*)(Wk + col * Dd + quar * 48);
        const float* qq = qT + quar * 48 * KP;
#pragma unroll 4
        for (int c = 0; c < 12; c++) {
            float4 w = __ldg(&w4[c]);
            fma12(a6, &qq[(4 * c + 0) * KP], pk2(w.x));
            fma12(a6, &qq[(4 * c + 1) * KP], pk2(w.y));
            fma12(a6, &qq[(4 * c + 2) * KP], pk2(w.z));
            fma12(a6, &qq[(4 * c + 3) * KP], pk2(w.w));
        }
        float qt[Kk];
        unpk11(a6, qt);
#pragma unroll
        for (int r = 0; r < Kk; r++) {
            qt[r] += __shfl_xor_sync(~0u, qt[r], 8);
            qt[r] += __shfl_xor_sync(~0u, qt[r], 16);
        }
        float lwv = lnw_in[col], lbv = lnb_in[col], bkv = bk[col];
        float ws[Kk], cp[Kk];
#pragma unroll
        for (int r = 0; r < Kk; r++) {
            float w2 = qt[r] * SCALEF * lwv;
            ws[r] = quar ? 0.f : w2;
            cp[r] = quar ? 0.f : (lbv * qt[r] + qa[r] * bkv) * SCALEF;
            if (quar == 0) g_w2k[(b * Kk + r) * Dd + col] = w2;
        }
#pragma unroll
        for (int r = 0; r < Kk; r++) {
            float a = ws[r], c = cp[r];
#pragma unroll
            for (int o = 16; o; o >>= 1) {
                a += __shfl_xor_sync(~0u, a, o);
                c += __shfl_xor_sync(~0u, c, o);
            }
            if (lane == 0) { atomicAdd(&red[r], a); atomicAdd(&red[12 + r], c); }
        }
    }
    __syncthreads();
    if (tid < Kk) {
        g_w2sum[b * Kk + tid] = red[tid];
        g_cc[b * Kk + tid] = red[12 + tid];
        g_s1[b * Kk + tid] = 0.f;
        g_s2[b * Kk + tid] = 0.f;
    }
    for (int i = tid; i < Kk * Dd; i += 768) g_R[b * Kk * Dd + i] = 0.f;
}

extern "C" void kernel_launch(void* const* d_in, const int* in_sizes, int n_in,
                              void* d_out, int out_size) {
    const float* inputs = (const float*)d_in[0];
    const float* noise = (const float*)d_in[1];
    const float* smu = (const float*)d_in[2];
    const float* ssig = (const float*)d_in[3];
    const float* ln_in_w = (const float*)d_in[4];
    const float* ln_in_b = (const float*)d_in[5];
    const float* ln_sl_w = (const float*)d_in[6];
    const float* ln_sl_b = (const float*)d_in[7];
    const float* ln_ml_w = (const float*)d_in[8];
    const float* ln_ml_b = (const float*)d_in[9];
    const float* Wq = (const float*)d_in[10];
    const float* bq = (const float*)d_in[11];
    const float* Wk = (const float*)d_in[12];
    const float* bk = (const float*)d_in[13];
    const float* Wv = (const float*)d_in[14];
    const float* bv = (const float*)d_in[15];
    const float* Wih = (const float*)d_in[16];
    const float* Whh = (const float*)d_in[17];
    const float* bih = (const float*)d_in[18];
    const float* bhh = (const float*)d_in[19];
    const float* W1 = (const float*)d_in[20];
    const float* b1 = (const float*)d_in[21];
    const float* W2 = (const float*)d_in[22];
    const float* b2 = (const float*)d_in[23];

    float* out = (float*)d_out;
    float* slots_out = out;
    float* attn_out = out + Bn * Kk * Dd;

    const int ATTN_SMEM = (Tt * XST + Kk * Dd) * 4;  // 108,800 bytes
    static bool attr_set = false;
    if (!attr_set) {
        cudaFuncSetAttribute(k_attn, cudaFuncAttributeMaxDynamicSharedMemorySize, ATTN_SMEM);
        attr_set = true;
    }

    k_init<<<384, 256>>>(noise, smu, ssig, Wq, Wv, W1, W2);
    k_pre<<<Bn, 192>>>(ln_sl_w, ln_sl_b, bq, Wk, bk, ln_in_w, ln_in_b);
    for (int it = 0; it < 3; it++) {
        int last = (it == 2) ? 1 : 0;
        k_attn<<<dim3(Nn / Tt, Bn), 256, ATTN_SMEM>>>(inputs, attn_out, last);
        k_gru<<<dim3(2, Bn), 576>>>(bv, Wih, Whh, bih, bhh, ln_in_w, ln_in_b);
        k_mlp<<<Bn, 768>>>(ln_ml_w, ln_ml_b, b1, b2, ln_sl_w, ln_sl_b, bq, Wk, bk,
                           ln_in_w, ln_in_b, slots_out, last);
    }
}

// round 16
// speedup vs baseline: 1.0605x; 1.0605x over previous
#include <cuda_runtime.h>

#define Bn 64
#define Nn 4096
#define Kk 11
#define KP 12
#define Dd 192
#define HIDn 128
#define Tt 128
#define XST 196
#define EPSF 1e-8f
#define LN_EPSF 1e-5f
#define SCALEF 0.07216878364870323f

typedef unsigned long long ull;

__device__ __forceinline__ ull pk2(float x) {
    ull r; asm("mov.b64 %0, {%1, %1};" : "=l"(r) : "f"(x)); return r;
}
__device__ __forceinline__ ull f2fma(ull a, ull b, ull c) {
    ull d; asm("fma.rn.f32x2 %0, %1, %2, %3;" : "=l"(d) : "l"(a), "l"(b), "l"(c)); return d;
}
__device__ __forceinline__ ull f2add(ull a, ull b) {
    ull d; asm("add.rn.f32x2 %0, %1, %2;" : "=l"(d) : "l"(a), "l"(b)); return d;
}
__device__ __forceinline__ float2 up2(ull v) {
    float lo, hi; asm("mov.b64 {%0, %1}, %2;" : "=f"(lo), "=f"(hi) : "l"(v));
    return make_float2(lo, hi);
}
__device__ __forceinline__ void fma12(ull acc[6], const float* p, ull xx) {
    ulonglong2 q0 = *(const ulonglong2*)p;
    ulonglong2 q1 = *(const ulonglong2*)(p + 4);
    ulonglong2 q2 = *(const ulonglong2*)(p + 8);
    acc[0] = f2fma(q0.x, xx, acc[0]); acc[1] = f2fma(q0.y, xx, acc[1]);
    acc[2] = f2fma(q1.x, xx, acc[2]); acc[3] = f2fma(q1.y, xx, acc[3]);
    acc[4] = f2fma(q2.x, xx, acc[4]); acc[5] = f2fma(q2.y, xx, acc[5]);
}
__device__ __forceinline__ void unpk11(const ull a6[6], float* o) {
#pragma unroll
    for (int j = 0; j < 6; j++) {
        float2 f = up2(a6[j]);
        o[2 * j] = f.x;
        if (2 * j + 1 < Kk) o[2 * j + 1] = f.y;
    }
}

__device__ float g_slots[Bn * Kk * Dd];
__device__ float g_h[Bn * Kk * Dd];
__device__ float g_w2k[Bn * Kk * Dd];
__device__ float g_w2sum[Bn * Kk];
__device__ float g_cc[Bn * Kk];
__device__ float g_R[Bn * Kk * Dd];
__device__ float g_s1[Bn * Kk];
__device__ float g_s2[Bn * Kk];
__device__ float g_WqT[Dd * Dd];
__device__ float g_WvT[Dd * Dd];
__device__ float g_W1T[HIDn * Dd];
__device__ float g_W2T[Dd * HIDn];

// ---------------- init ----------------
__global__ void k_init(const float* __restrict__ noise, const float* __restrict__ smu,
                       const float* __restrict__ ssig, const float* __restrict__ Wq,
                       const float* __restrict__ Wv, const float* __restrict__ W1,
                       const float* __restrict__ W2) {
    const int T0 = Bn * Kk * Dd;
    const int T1 = T0 + Dd * Dd;
    const int T2 = T1 + Dd * Dd;
    const int T3 = T2 + Dd * HIDn;
    const int T4 = T3 + HIDn * Dd;
    for (int i = blockIdx.x * blockDim.x + threadIdx.x; i < T4; i += gridDim.x * blockDim.x) {
        if (i < T0) { int d = i % Dd; g_slots[i] = smu[d] + ssig[d] * noise[i]; }
        else if (i < T1) { int i2 = i - T0; g_WqT[(i2 % Dd) * Dd + i2 / Dd] = Wq[i2]; }
        else if (i < T2) { int i2 = i - T1; g_WvT[(i2 % Dd) * Dd + i2 / Dd] = Wv[i2]; }
        else if (i < T3) { int i2 = i - T2; g_W1T[(i2 % HIDn) * Dd + i2 / HIDn] = W1[i2]; }
        else { int i2 = i - T3; g_W2T[(i2 % Dd) * HIDn + i2 / Dd] = W2[i2]; }
    }
}

// ---------------- iter-0 slot preprocessing ----------------
__global__ __launch_bounds__(192) void k_pre(const float* __restrict__ lnw_s,
                                             const float* __restrict__ lnb_s,
                                             const float* __restrict__ bq,
                                             const float* __restrict__ Wk,
                                             const float* __restrict__ bk,
                                             const float* __restrict__ lnw_in,
                                             const float* __restrict__ lnb_in) {
    __shared__ float snt[Dd * KP];
    __shared__ float qT[Dd * KP];
    __shared__ float red[24];
    int b = blockIdx.x, t = threadIdx.x, wid = t >> 5, lane = t & 31;
    if (t < 24) red[t] = 0.f;
    snt[t * KP + 11] = 0.f;

    for (int r = wid; r < Kk; r += 6) {
        float v[6], s = 0.f;
#pragma unroll
        for (int i = 0; i < 6; i++) { v[i] = g_slots[(b * Kk + r) * Dd + lane + 32 * i]; s += v[i]; }
#pragma unroll
        for (int o = 16; o; o >>= 1) s += __shfl_xor_sync(~0u, s, o);
        float mu = s * (1.0f / Dd), q = 0.f;
#pragma unroll
        for (int i = 0; i < 6; i++) { float d = v[i] - mu; q += d * d; }
#pragma unroll
        for (int o = 16; o; o >>= 1) q += __shfl_xor_sync(~0u, q, o);
        float rstd = rsqrtf(q * (1.0f / Dd) + LN_EPSF);
#pragma unroll
        for (int i = 0; i < 6; i++) {
            int d = lane + 32 * i;
            snt[d * KP + r] = (v[i] - mu) * rstd * lnw_s[d] + lnb_s[d];
        }
    }
    __syncthreads();

    ull a6[6];
#pragma unroll
    for (int j = 0; j < 6; j++) a6[j] = 0ull;
    {
        const float4* w4 = (const float4*)(g_WqT + t * Dd);
#pragma unroll 4
        for (int c = 0; c < 48; c++) {
            float4 w = __ldg(&w4[c]);
            fma12(a6, &snt[(4 * c + 0) * KP], pk2(w.x));
            fma12(a6, &snt[(4 * c + 1) * KP], pk2(w.y));
            fma12(a6, &snt[(4 * c + 2) * KP], pk2(w.z));
            fma12(a6, &snt[(4 * c + 3) * KP], pk2(w.w));
        }
    }
    float qa[Kk];
    unpk11(a6, qa);
    float bqv = bq[t];
#pragma unroll
    for (int r = 0; r < Kk; r++) { qa[r] += bqv; qT[t * KP + r] = qa[r]; }
    qT[t * KP + 11] = 0.f;
    __syncthreads();

#pragma unroll
    for (int j = 0; j < 6; j++) a6[j] = 0ull;
    {
        const float4* w4 = (const float4*)(Wk + t * Dd);
#pragma unroll 4
        for (int c = 0; c < 48; c++) {
            float4 w = __ldg(&w4[c]);
            fma12(a6, &qT[(4 * c + 0) * KP], pk2(w.x));
            fma12(a6, &qT[(4 * c + 1) * KP], pk2(w.y));
            fma12(a6, &qT[(4 * c + 2) * KP], pk2(w.z));
            fma12(a6, &qT[(4 * c + 3) * KP], pk2(w.w));
        }
    }
    float qt[Kk];
    unpk11(a6, qt);
    float lwv = lnw_in[t], lbv = lnb_in[t], bkv = bk[t];
    float ws[Kk], cp[Kk];
#pragma unroll
    for (int r = 0; r < Kk; r++) {
        float w2 = qt[r] * SCALEF * lwv;
        g_w2k[(b * Kk + r) * Dd + t] = w2;
        ws[r] = w2;
        cp[r] = (lbv * qt[r] + qa[r] * bkv) * SCALEF;
    }
#pragma unroll
    for (int r = 0; r < Kk; r++) {
        float a = ws[r], c = cp[r];
#pragma unroll
        for (int o = 16; o; o >>= 1) {
            a += __shfl_xor_sync(~0u, a, o);
            c += __shfl_xor_sync(~0u, c, o);
        }
        if (lane == 0) { atomicAdd(&red[r], a); atomicAdd(&red[12 + r], c); }
    }
    __syncthreads();
    if (t < Kk) {
        g_w2sum[b * Kk + t] = red[t];
        g_cc[b * Kk + t] = red[12 + t];
        g_s1[b * Kk + t] = 0.f;
        g_s2[b * Kk + t] = 0.f;
    }
    for (int i = t; i < Kk * Dd; i += 192) g_R[b * Kk * Dd + i] = 0.f;
}

// ---------------- attention pass: R9 structure, unroll 4 for deeper MLP --------
__global__ __launch_bounds__(256, 2) void k_attn(const float* __restrict__ x,
                                                 float* __restrict__ attn_out, int wr) {
    extern __shared__ float sm[];
    float* Xs = sm;
    float* Ws = sm + Tt * XST;
    float* A1 = Ws;
    int b = blockIdx.y, tid = threadIdx.x;
    int lane = tid & 31, warp = tid >> 5;
    int half = lane >> 4;
    int t = warp * 16 + (lane & 15);
    int n0 = blockIdx.x * Tt;

    const float* xb = x + ((size_t)(b * Nn + n0)) * Dd;
    for (int i = tid * 4; i < Tt * Dd; i += 256 * 4) {
        float4 v = __ldcs((const float4*)(xb + i));
        int tt = i / Dd, d = i - tt * Dd;
        *(float4*)&Xs[tt * XST + d] = v;
    }
    const float* wsrc = g_w2k + b * Kk * Dd;
    for (int i = tid; i < Kk * Dd; i += 256) Ws[i] = wsrc[i];
    __syncthreads();

    ull aA[Kk], aB[Kk];
#pragma unroll
    for (int k = 0; k < Kk; k++) { aA[k] = 0ull; aB[k] = 0ull; }
    ull sS = 0ull, sQ = 0ull;
    const int cbase = half * 96;
    const ulonglong2* xr2 = (const ulonglong2*)(Xs + t * XST + cbase);
#pragma unroll 4
    for (int c = 0; c < 24; c++) {
        ulonglong2 xv = xr2[c];
        sS = f2add(sS, f2add(xv.x, xv.y));
        sQ = f2fma(xv.x, xv.x, sQ); sQ = f2fma(xv.y, xv.y, sQ);
        const float* wrow = &Ws[cbase + c * 4];
#pragma unroll
        for (int k = 0; k < Kk; k++) {
            ulonglong2 wv = *(const ulonglong2*)&wrow[k * Dd];
            aA[k] = f2fma(xv.x, wv.x, aA[k]);
            aB[k] = f2fma(xv.y, wv.y, aB[k]);
        }
    }
    float dots[Kk];
#pragma unroll
    for (int k = 0; k < Kk; k++) {
        float2 fa = up2(aA[k]), fb = up2(aB[k]);
        dots[k] = (fa.x + fa.y) + (fb.x + fb.y);
    }
    float2 sf = up2(sS), qf = up2(sQ);
    float sSf = sf.x + sf.y, sQf = qf.x + qf.y;
    sSf += __shfl_xor_sync(~0u, sSf, 16);
    sQf += __shfl_xor_sync(~0u, sQf, 16);
#pragma unroll
    for (int k = 0; k < Kk; k++) dots[k] += __shfl_xor_sync(~0u, dots[k], 16);

    float mu = sSf * (1.0f / Dd);
    float rs = rsqrtf(sQf * (1.0f / Dd) - mu * mu + LN_EPSF);
    float rm = rs * mu;
    float dk[Kk];
#pragma unroll
    for (int k = 0; k < Kk; k++)
        dk[k] = rs * dots[k] - rm * __ldg(&g_w2sum[b * Kk + k]) + __ldg(&g_cc[b * Kk + k]);
    float mx = dk[0];
#pragma unroll
    for (int k = 1; k < Kk; k++) mx = fmaxf(mx, dk[k]);
    float sum = 0.f;
#pragma unroll
    for (int k = 0; k < Kk; k++) { dk[k] = __expf(dk[k] - mx); sum += dk[k]; }
    float inv = __fdividef(1.0f, sum);
#pragma unroll
    for (int k = 0; k < Kk; k++) dk[k] = fmaf(dk[k], inv, EPSF);

    if (wr && half == 0) {
        int n = n0 + t;
#pragma unroll
        for (int k = 0; k < Kk; k++)
            attn_out[((size_t)(b * Kk + k)) * Nn + n] = dk[k];
    }
#pragma unroll
    for (int k = 0; k < Kk; k++) {
        float s1v = half ? 0.f : dk[k];
        float s2v = half ? 0.f : dk[k] * rm;
#pragma unroll
        for (int o = 16; o; o >>= 1) {
            s1v += __shfl_xor_sync(~0u, s1v, o);
            s2v += __shfl_xor_sync(~0u, s2v, o);
        }
        if (lane == 0) {
            atomicAdd(&g_s1[b * Kk + k], s1v);
            atomicAdd(&g_s2[b * Kk + k], s2v);
        }
    }
    __syncthreads();
    if (half == 0) {
#pragma unroll
        for (int k = 0; k < Kk; k++) A1[t * KP + k] = dk[k] * rs;
        A1[t * KP + 11] = 0.f;
    }
    __syncthreads();

    float* Rb = g_R + b * Kk * Dd;
    for (int w = tid; w < 384; w += 256) {
        int h = (w >= 192) ? 1 : 0;
        int d = w - h * 192;
        ull c6[6];
#pragma unroll
        for (int j = 0; j < 6; j++) c6[j] = 0ull;
        int t0 = h * 64;
#pragma unroll 4
        for (int tt = t0; tt < t0 + 64; tt++) {
            fma12(c6, &A1[tt * KP], pk2(Xs[tt * XST + d]));
        }
#pragma unroll
        for (int j = 0; j < 6; j++) {
            float2 f = up2(c6[j]);
            atomicAdd(&Rb[(2 * j) * Dd + d], f.x);
            if (2 * j + 1 < Kk) atomicAdd(&Rb[(2 * j + 1) * Dd + d], f.y);
        }
    }
}

// ---------------- GRU: R13-exact (576 threads, lane-pair e-split) ----------------
__global__ __launch_bounds__(576) void k_gru(const float* __restrict__ bv,
                                             const float* __restrict__ Wih,
                                             const float* __restrict__ Whh,
                                             const float* __restrict__ bih,
                                             const float* __restrict__ bhh,
                                             const float* __restrict__ lnw_in,
                                             const float* __restrict__ lnb_in) {
    __shared__ float uT[Dd * KP], spT[Dd * KP], vT[Dd * KP];
    __shared__ float P0[96 * KP], P1[96 * KP], PXn[96 * KP], PHn[96 * KP];
    __shared__ float sinv[Kk], s2s[Kk];
    int hh = blockIdx.x, b = blockIdx.y, tid = threadIdx.x;
    int lane = tid & 31, warp = tid >> 5;
    int half = lane >> 4;
    int col = warp * 16 + (lane & 15);

    if (tid < Kk) {
        sinv[tid] = __fdividef(1.0f, g_s1[b * Kk + tid]);
        s2s[tid] = g_s2[b * Kk + tid];
    }
    __syncthreads();
    for (int i = tid; i < Dd; i += 576) { uT[i * KP + 11] = 0.f; spT[i * KP + 11] = 0.f; }
    for (int i = tid; i < Kk * Dd; i += 576) {
        int r = i / Dd, d = i - r * Dd;
        float R = g_R[b * Kk * Dd + i];
        uT[d * KP + r] = lnw_in[d] * (R - s2s[r]) * sinv[r] + lnb_in[d];
        spT[d * KP + r] = g_slots[b * Kk * Dd + i];
    }
    __syncthreads();

    if (col < Dd) {
        ull a6[6];
#pragma unroll
        for (int j = 0; j < 6; j++) a6[j] = 0ull;
        const float4* w4 = (const float4*)(g_WvT + col * Dd + half * 96);
        const float* uu = uT + half * 96 * KP;
#pragma unroll 4
        for (int c = 0; c < 24; c++) {
            float4 w = __ldg(&w4[c]);
            fma12(a6, &uu[(4 * c + 0) * KP], pk2(w.x));
            fma12(a6, &uu[(4 * c + 1) * KP], pk2(w.y));
            fma12(a6, &uu[(4 * c + 2) * KP], pk2(w.z));
            fma12(a6, &uu[(4 * c + 3) * KP], pk2(w.w));
        }
        float vv[Kk];
        unpk11(a6, vv);
#pragma unroll
        for (int r = 0; r < Kk; r++) vv[r] += __shfl_xor_sync(~0u, vv[r], 16);
        if (half == 0) {
            float bvv = bv[col];
#pragma unroll
            for (int r = 0; r < Kk; r++) vT[col * KP + r] = vv[r] + bvv;
            vT[col * KP + 11] = 0.f;
        }
    }
    __syncthreads();

    {
        int g = col / 96, tl = col - g * 96;
        int j = g * Dd + hh * 96 + tl;
        ull ax6[6], ah6[6];
#pragma unroll
        for (int jj = 0; jj < 6; jj++) { ax6[jj] = 0ull; ah6[jj] = 0ull; }
        const float4* wi4 = (const float4*)(Wih + j * Dd + half * 96);
        const float4* wh4 = (const float4*)(Whh + j * Dd + half * 96);
        const float* vv_ = vT + half * 96 * KP;
        const float* ss_ = spT + half * 96 * KP;
#pragma unroll 4
        for (int c = 0; c < 24; c++) {
            float4 wi = __ldg(&wi4[c]);
            float4 wh = __ldg(&wh4[c]);
            fma12(ax6, &vv_[(4 * c + 0) * KP], pk2(wi.x));
            fma12(ax6, &vv_[(4 * c + 1) * KP], pk2(wi.y));
            fma12(ax6, &vv_[(4 * c + 2) * KP], pk2(wi.z));
            fma12(ax6, &vv_[(4 * c + 3) * KP], pk2(wi.w));
            fma12(ah6, &ss_[(4 * c + 0) * KP], pk2(wh.x));
            fma12(ah6, &ss_[(4 * c + 1) * KP], pk2(wh.y));
            fma12(ah6, &ss_[(4 * c + 2) * KP], pk2(wh.z));
            fma12(ah6, &ss_[(4 * c + 3) * KP], pk2(wh.w));
        }
        float axf[Kk], ahf[Kk];
        unpk11(ax6, axf); unpk11(ah6, ahf);
#pragma unroll
        for (int r = 0; r < Kk; r++) {
            axf[r] += __shfl_xor_sync(~0u, axf[r], 16);
            ahf[r] += __shfl_xor_sync(~0u, ahf[r], 16);
        }
        if (half == 0) {
            float bi = bih[j], bh = bhh[j];
            if (g == 0) {
#pragma unroll
                for (int r = 0; r < Kk; r++) P0[tl * KP + r] = axf[r] + ahf[r] + bi + bh;
            } else if (g == 1) {
#pragma unroll
                for (int r = 0; r < Kk; r++) P1[tl * KP + r] = axf[r] + ahf[r] + bi + bh;
            } else {
#pragma unroll
                for (int r = 0; r < Kk; r++) { PXn[tl * KP + r] = axf[r] + bi; PHn[tl * KP + r] = ahf[r] + bh; }
            }
        }
    }
    __syncthreads();
    for (int i = tid; i < Kk * 96; i += 576) {
        int r = i / 96, tl2 = i - r * 96, tg = hh * 96 + tl2;
        float rg = 1.0f / (1.0f + __expf(-P0[tl2 * KP + r]));
        float zg = 1.0f / (1.0f + __expf(-P1[tl2 * KP + r]));
        float ng = tanhf(fmaf(rg, PHn[tl2 * KP + r], PXn[tl2 * KP + r]));
        float hp = spT[tg * KP + r];
        g_h[(b * Kk + r) * Dd + tg] = (1.0f - zg) * ng + zg * hp;
    }
}

// -------- LN + MLP + residual + fused pre: R14-exact (384 threads, lane-pair) --------
__global__ __launch_bounds__(384) void k_mlp(const float* __restrict__ lnw_m,
                                             const float* __restrict__ lnb_m,
                                             const float* __restrict__ b1,
                                             const float* __restrict__ b2,
                                             const float* __restrict__ lnw_s,
                                             const float* __restrict__ lnb_s,
                                             const float* __restrict__ bq,
                                             const float* __restrict__ Wk,
                                             const float* __restrict__ bk,
                                             const float* __restrict__ lnw_in,
                                             const float* __restrict__ lnb_in,
                                             float* __restrict__ slots_out, int last) {
    __shared__ float hT[Dd * KP];
    __shared__ float m1T[HIDn * KP];
    __shared__ float snt[Dd * KP];
    __shared__ float qT[Dd * KP];
    __shared__ float red[24];
    int b = blockIdx.x, tid = threadIdx.x;
    int lane = tid & 31, warp = tid >> 5;
    int half = lane >> 4;
    int col = warp * 16 + (lane & 15);
    if (tid < 24) red[tid] = 0.f;
    if (tid < Dd) { hT[tid * KP + 11] = 0.f; snt[tid * KP + 11] = 0.f; }
    if (tid < HIDn) m1T[tid * KP + 11] = 0.f;

    if (warp < Kk) {
        int r = warp;
        float v[6], s = 0.f;
#pragma unroll
        for (int i = 0; i < 6; i++) { v[i] = g_h[(b * Kk + r) * Dd + lane + 32 * i]; s += v[i]; }
#pragma unroll
        for (int o = 16; o; o >>= 1) s += __shfl_xor_sync(~0u, s, o);
        float mu = s * (1.0f / Dd), q = 0.f;
#pragma unroll
        for (int i = 0; i < 6; i++) { float d = v[i] - mu; q += d * d; }
#pragma unroll
        for (int o = 16; o; o >>= 1) q += __shfl_xor_sync(~0u, q, o);
        float rstd = rsqrtf(q * (1.0f / Dd) + LN_EPSF);
#pragma unroll
        for (int i = 0; i < 6; i++) {
            int d = lane + 32 * i;
            hT[d * KP + r] = (v[i] - mu) * rstd * lnw_m[d] + lnb_m[d];
        }
    }
    __syncthreads();

    if (col < HIDn) {
        ull a6[6];
#pragma unroll
        for (int j = 0; j < 6; j++) a6[j] = 0ull;
        const float4* w4 = (const float4*)(g_W1T + col * Dd + half * 96);
        const float* hh_ = hT + half * 96 * KP;
#pragma unroll 4
        for (int c = 0; c < 24; c++) {
            float4 w = __ldg(&w4[c]);
            fma12(a6, &hh_[(4 * c + 0) * KP], pk2(w.x));
            fma12(a6, &hh_[(4 * c + 1) * KP], pk2(w.y));
            fma12(a6, &hh_[(4 * c + 2) * KP], pk2(w.z));
            fma12(a6, &hh_[(4 * c + 3) * KP], pk2(w.w));
        }
        float vv[Kk];
        unpk11(a6, vv);
#pragma unroll
        for (int r = 0; r < Kk; r++) vv[r] += __shfl_xor_sync(~0u, vv[r], 16);
        if (half == 0) {
            float b1v = b1[col];
#pragma unroll
            for (int r = 0; r < Kk; r++) m1T[col * KP + r] = fmaxf(vv[r] + b1v, 0.0f);
        }
    }
    __syncthreads();

    {
        ull a6[6];
#pragma unroll
        for (int j = 0; j < 6; j++) a6[j] = 0ull;
        const float4* w4 = (const float4*)(g_W2T + col * HIDn + half * 64);
        const float* mm = m1T + half * 64 * KP;
#pragma unroll 4
        for (int c = 0; c < 16; c++) {
            float4 w = __ldg(&w4[c]);
            fma12(a6, &mm[(4 * c + 0) * KP], pk2(w.x));
            fma12(a6, &mm[(4 * c + 1) * KP], pk2(w.y));
            fma12(a6, &mm[(4 * c + 2) * KP], pk2(w.z));
            fma12(a6, &mm[(4 * c + 3) * KP], pk2(w.w));
        }
        float acc[Kk];
        unpk11(a6, acc);
#pragma unroll
        for (int r = 0; r < Kk; r++) acc[r] += __shfl_xor_sync(~0u, acc[r], 16);
        if (half == 0) {
            float b2v = b2[col];
#pragma unroll
            for (int r = 0; r < Kk; r++) {
                float o = g_h[(b * Kk + r) * Dd + col] + acc[r] + b2v;
                g_slots[(b * Kk + r) * Dd + col] = o;
                if (last) slots_out[(b * Kk + r) * Dd + col] = o;
                hT[col * KP + r] = o;
            }
        }
    }
    if (last) return;
    __syncthreads();

    if (warp < Kk) {
        int r = warp;
        float v[6], s = 0.f;
#pragma unroll
        for (int i = 0; i < 6; i++) { v[i] = hT[(lane + 32 * i) * KP + r]; s += v[i]; }
#pragma unroll
        for (int o = 16; o; o >>= 1) s += __shfl_xor_sync(~0u, s, o);
        float mu = s * (1.0f / Dd), q = 0.f;
#pragma unroll
        for (int i = 0; i < 6; i++) { float d = v[i] - mu; q += d * d; }
#pragma unroll
        for (int o = 16; o; o >>= 1) q += __shfl_xor_sync(~0u, q, o);
        float rstd = rsqrtf(q * (1.0f / Dd) + LN_EPSF);
#pragma unroll
        for (int i = 0; i < 6; i++) {
            int d = lane + 32 * i;
            snt[d * KP + r] = (v[i] - mu) * rstd * lnw_s[d] + lnb_s[d];
        }
    }
    __syncthreads();
    float qa[Kk];
    {
        ull a6[6];
#pragma unroll
        for (int j = 0; j < 6; j++) a6[j] = 0ull;
        const float4* w4 = (const float4*)(g_WqT + col * Dd + half * 96);
        const float* ss = snt + half * 96 * KP;
#pragma unroll 4
        for (int c = 0; c < 24; c++) {
            float4 w = __ldg(&w4[c]);
            fma12(a6, &ss[(4 * c + 0) * KP], pk2(w.x));
            fma12(a6, &ss[(4 * c + 1) * KP], pk2(w.y));
            fma12(a6, &ss[(4 * c + 2) * KP], pk2(w.z));
            fma12(a6, &ss[(4 * c + 3) * KP], pk2(w.w));
        }
        unpk11(a6, qa);
        float bqv = bq[col];
#pragma unroll
        for (int r = 0; r < Kk; r++) {
            qa[r] += __shfl_xor_sync(~0u, qa[r], 16);
            qa[r] += bqv;
        }
        if (half == 0) {
#pragma unroll
            for (int r = 0; r < Kk; r++) qT[col * KP + r] = qa[r];
            qT[col * KP + 11] = 0.f;
        }
    }
    __syncthreads();
    {
        ull a6[6];
#pragma unroll
        for (int j = 0; j < 6; j++) a6[j] = 0ull;
        const float4* w4 = (const float4*)(Wk + col * Dd + half * 96);
        const float* qq = qT + half * 96 * KP;
#pragma unroll 4
        for (int c = 0; c < 24; c++) {
            float4 w = __ldg(&w4[c]);
            fma12(a6, &qq[(4 * c + 0) * KP], pk2(w.x));
            fma12(a6, &qq[(4 * c + 1) * KP], pk2(w.y));
            fma12(a6, &qq[(4 * c + 2) * KP], pk2(w.z));
            fma12(a6, &qq[(4 * c + 3) * KP], pk2(w.w));
        }
        float qt[Kk];
        unpk11(a6, qt);
#pragma unroll
        for (int r = 0; r < Kk; r++) qt[r] += __shfl_xor_sync(~0u, qt[r], 16);
        float lwv = lnw_in[col], lbv = lnb_in[col], bkv = bk[col];
        float ws[Kk], cp[Kk];
#pragma unroll
        for (int r = 0; r < Kk; r++) {
            float w2 = qt[r] * SCALEF * lwv;
            ws[r] = half ? 0.f : w2;
            cp[r] = half ? 0.f : (lbv * qt[r] + qa[r] * bkv) * SCALEF;
            if (half == 0) g_w2k[(b * Kk + r) * Dd + col] = w2;
        }
#pragma unroll
        for (int r = 0; r < Kk; r++) {
            float a = ws[r], c = cp[r];
#pragma unroll
            for (int o = 16; o; o >>= 1) {
                a += __shfl_xor_sync(~0u, a, o);
                c += __shfl_xor_sync(~0u, c, o);
            }
            if (lane == 0) { atomicAdd(&red[r], a); atomicAdd(&red[12 + r], c); }
        }
    }
    __syncthreads();
    if (tid < Kk) {
        g_w2sum[b * Kk + tid] = red[tid];
        g_cc[b * Kk + tid] = red[12 + tid];
        g_s1[b * Kk + tid] = 0.f;
        g_s2[b * Kk + tid] = 0.f;
    }
    for (int i = tid; i < Kk * Dd; i += 384) g_R[b * Kk * Dd + i] = 0.f;
}

extern "C" void kernel_launch(void* const* d_in, const int* in_sizes, int n_in,
                              void* d_out, int out_size) {
    const float* inputs = (const float*)d_in[0];
    const float* noise = (const float*)d_in[1];
    const float* smu = (const float*)d_in[2];
    const float* ssig = (const float*)d_in[3];
    const float* ln_in_w = (const float*)d_in[4];
    const float* ln_in_b = (const float*)d_in[5];
    const float* ln_sl_w = (const float*)d_in[6];
    const float* ln_sl_b = (const float*)d_in[7];
    const float* ln_ml_w = (const float*)d_in[8];
    const float* ln_ml_b = (const float*)d_in[9];
    const float* Wq = (const float*)d_in[10];
    const float* bq = (const float*)d_in[11];
    const float* Wk = (const float*)d_in[12];
    const float* bk = (const float*)d_in[13];
    const float* Wv = (const float*)d_in[14];
    const float* bv = (const float*)d_in[15];
    const float* Wih = (const float*)d_in[16];
    const float* Whh = (const float*)d_in[17];
    const float* bih = (const float*)d_in[18];
    const float* bhh = (const float*)d_in[19];
    const float* W1 = (const float*)d_in[20];
    const float* b1 = (const float*)d_in[21];
    const float* W2 = (const float*)d_in[22];
    const float* b2 = (const float*)d_in[23];

    float* out = (float*)d_out;
    float* slots_out = out;
    float* attn_out = out + Bn * Kk * Dd;

    const int ATTN_SMEM = (Tt * XST + Kk * Dd) * 4;  // 108,800 bytes
    static bool attr_set = false;
    if (!attr_set) {
        cudaFuncSetAttribute(k_attn, cudaFuncAttributeMaxDynamicSharedMemorySize, ATTN_SMEM);
        attr_set = true;
    }

    k_init<<<384, 256>>>(noise, smu, ssig, Wq, Wv, W1, W2);
    k_pre<<<Bn, 192>>>(ln_sl_w, ln_sl_b, bq, Wk, bk, ln_in_w, ln_in_b);
    for (int it = 0; it < 3; it++) {
        int last = (it == 2) ? 1 : 0;
        k_attn<<<dim3(Nn / Tt, Bn), 256, ATTN_SMEM>>>(inputs, attn_out, last);
        k_gru<<<dim3(2, Bn), 576>>>(bv, Wih, Whh, bih, bhh, ln_in_w, ln_in_b);
        k_mlp<<<Bn, 384>>>(ln_ml_w, ln_ml_b, b1, b2, ln_sl_w, ln_sl_b, bq, Wk, bk,
                           ln_in_w, ln_in_b, slots_out, last);
    }
}